// round 17
// baseline (speedup 1.0000x reference)
#include <cuda_runtime.h>
#include <cuda_fp16.h>
#include <cstdint>

#define BATCH 4096
#define NST   512
#define IO    16
#define DS    32
#define PTOT  8192
#define NCH   32
#define LCH   16

typedef unsigned long long ull;

// ---------------- device scratch (static; no mallocs) ----------------
__device__ __align__(16) __half g_Uh[(size_t)BATCH * PTOT];            // fp16(U), written by gemm1
__device__ __align__(16) __half g_Th[(size_t)NCH * 256 * 320];         // T^T per chunk [n][k]
__device__ __align__(16) __half g_Sh[(size_t)NCH * 64 * 256];          // S^T per chunk [n][k]
__device__ __align__(16) float g_xloc[(size_t)BATCH * NCH * 64];       // [row][c][64]
__device__ __align__(16) __half g_xinh[(size_t)BATCH * NCH * 64];      // fp16(xin)
__device__ float g_P2[2 * NCH * DS * DS];

// ---------------- cp.async helpers ----------------
__device__ __forceinline__ void cpasync16(void* s, const void* g) {
    uint32_t sa = (uint32_t)__cvta_generic_to_shared(s);
    asm volatile("cp.async.cg.shared.global [%0], [%1], 16;" :: "r"(sa), "l"(g));
}
__device__ __forceinline__ void cpcommit() { asm volatile("cp.async.commit_group;"); }
template<int N> __device__ __forceinline__ void cpwait() {
    asm volatile("cp.async.wait_group %0;" :: "n"(N));
}

// ---------------- mma.sync / ldmatrix helpers (fp16) ----------------
__device__ __forceinline__ void ldmx4(uint32_t* r, uint32_t addr) {
    asm volatile("ldmatrix.sync.aligned.m8n8.x4.shared.b16 {%0,%1,%2,%3}, [%4];"
        : "=r"(r[0]), "=r"(r[1]), "=r"(r[2]), "=r"(r[3]) : "r"(addr));
}
__device__ __forceinline__ void ldmx2(uint32_t* r, uint32_t addr) {
    asm volatile("ldmatrix.sync.aligned.m8n8.x2.shared.b16 {%0,%1}, [%2];"
        : "=r"(r[0]), "=r"(r[1]) : "r"(addr));
}
__device__ __forceinline__ void mma16816(float* c, const uint32_t* a, const uint32_t* b) {
    asm volatile(
        "mma.sync.aligned.m16n8k16.row.col.f32.f16.f16.f32 "
        "{%0,%1,%2,%3}, {%4,%5,%6,%7}, {%8,%9}, {%0,%1,%2,%3};"
        : "+f"(c[0]), "+f"(c[1]), "+f"(c[2]), "+f"(c[3])
        : "r"(a[0]), "r"(a[1]), "r"(a[2]), "r"(a[3]), "r"(b[0]), "r"(b[1]));
}
// swizzled smem offset: logical (row r, 16B chunk k8) in a [*,64]fp16 tile
__device__ __forceinline__ uint32_t swz(int r, int k8) {
    return (uint32_t)(r * 128 + ((k8 ^ (r & 7)) << 4));
}
__device__ __forceinline__ uint32_t h2u(__half2 h) {
    uint32_t r; memcpy(&r, &h, 4); return r;
}

// =====================================================================
// 1. Strip precompute -> T^T (fp16) input blocks + S^T columns
// =====================================================================
__global__ __launch_bounds__(128)
void strip_kernel(const float* __restrict__ A, const float* __restrict__ B,
                  const float* __restrict__ C, const float* __restrict__ D,
                  const float* __restrict__ E, const float* __restrict__ F,
                  const float* __restrict__ G) {
    __shared__ float sV[2][DS][IO];
    __shared__ float sW2[DS][DS];
    __shared__ float sW1[IO][DS];
    const int tid = threadIdx.x;
    const int c = blockIdx.x, s = blockIdx.y, d = blockIdx.z;
    const int k0 = c * LCH;
    __half* Th = g_Th + (size_t)c * 256 * 320;

    const float* src0 = ((d == 0) ? B : F) + (size_t)(k0 + s) * 512;
    for (int e = tid; e < 512; e += 128) sV[0][e >> 4][e & 15] = src0[e];
    if (d == 0) {
        const float* Ds = D + (size_t)(k0 + s) * 256;
        for (int e = tid; e < 256; e += 128) {
            const int o = e >> 4, i = e & 15;
            Th[(size_t)(s * 16 + o) * 320 + s * 16 + i] = __float2half_rn(Ds[o * 16 + i]);
        }
    }
    __syncthreads();

    int pb = 0;
    const int nsteps = (d == 0) ? (LCH - 1 - s) : s;
    for (int step = 0; step < nsteps; ++step) {
        const int t = (d == 0) ? (s + 1 + step) : (s - 1 - step);
        const int k = k0 + t;
        const float* W2 = ((d == 0) ? A : E) + (size_t)k * 1024;
        const float* W1 = ((d == 0) ? C : G) + (size_t)k * 512;
        for (int e = tid; e < 1024; e += 128) sW2[e >> 5][e & 31] = W2[e];
        for (int e = tid; e < 512;  e += 128) sW1[e >> 5][e & 31] = W1[e];
        __syncthreads();
        for (int e = tid; e < 256; e += 128) {
            const int o = e >> 4, i = e & 15;
            float acc = 0.f;
#pragma unroll
            for (int l = 0; l < DS; ++l) acc += sW1[o][l] * sV[pb][l][i];
            Th[(size_t)(t * 16 + o) * 320 + s * 16 + i] = __float2half_rn(acc);
        }
        for (int e = tid; e < 512; e += 128) {
            const int j = e >> 4, i = e & 15;
            float acc = 0.f;
#pragma unroll
            for (int l = 0; l < DS; ++l) acc += sW2[j][l] * sV[pb][l][i];
            sV[pb ^ 1][j][i] = acc;
        }
        __syncthreads();
        pb ^= 1;
    }
    for (int e = tid; e < 512; e += 128) {
        const int j = e >> 4, i = e & 15;
        g_Sh[(size_t)c * 64 * 256 + (size_t)(d * 32 + j) * 256 + s * 16 + i] =
            __float2half_rn(sV[pb][j][i]);
    }
}

// =====================================================================
// 2. M/N correction rows of T^T + propagators
// =====================================================================
__global__ __launch_bounds__(256)
void mn_kernel(const float* __restrict__ A, const float* __restrict__ C,
               const float* __restrict__ E, const float* __restrict__ G) {
    __shared__ float sV[2][DS][DS];
    __shared__ float sW2[DS][DS];
    __shared__ float sW1[IO][DS];
    const int tid = threadIdx.x;
    const int c = blockIdx.x, d = blockIdx.y;
    const int k0 = c * LCH;
    __half* Th = g_Th + (size_t)c * 256 * 320;

    for (int e = tid; e < 1024; e += 256)
        sV[0][e >> 5][e & 31] = ((e >> 5) == (e & 31)) ? 1.f : 0.f;
    __syncthreads();

    int pb = 0;
    for (int step = 0; step < LCH; ++step) {
        const int t = (d == 0) ? step : (LCH - 1 - step);
        const int k = k0 + t;
        const float* W2 = ((d == 0) ? A : E) + (size_t)k * 1024;
        const float* W1 = ((d == 0) ? C : G) + (size_t)k * 512;
        for (int e = tid; e < 1024; e += 256) sW2[e >> 5][e & 31] = W2[e];
        for (int e = tid; e < 512;  e += 256) sW1[e >> 5][e & 31] = W1[e];
        __syncthreads();
        for (int e = tid; e < 512; e += 256) {
            const int o = e >> 5, j = e & 31;
            float acc = 0.f;
#pragma unroll
            for (int l = 0; l < DS; ++l) acc += sW1[o][l] * sV[pb][l][j];
            Th[(size_t)(t * 16 + o) * 320 + 256 + d * 32 + j] = __float2half_rn(acc);
        }
        for (int e = tid; e < 1024; e += 256) {
            const int i = e >> 5, j = e & 31;
            float acc = 0.f;
#pragma unroll
            for (int l = 0; l < DS; ++l) acc += sW2[i][l] * sV[pb][l][j];
            sV[pb ^ 1][i][j] = acc;
        }
        __syncthreads();
        pb ^= 1;
    }
    for (int e = tid; e < 1024; e += 256) {
        const int i = e >> 5, j = e & 31;
        g_P2[(size_t)(d * NCH + c) * 1024 + j * 32 + i] = sV[pb][i][j];
    }
}

// =====================================================================
// 3. GEMM1 (fp16 single-term, fused U-convert):
//    xloc[128x64] = fp16(U)[128x256] x Sh^T ; also writes g_Uh.
//    stage 58KB = Af32 34816(pad 272B/row) | Ah 16K | Bh 8K; 2 stages.
// =====================================================================
#define G1S 59392
#define AH_OFF 34816
#define BH_OFF 51200
__global__ __launch_bounds__(128)
void gemm1_kernel(const float* __restrict__ U) {
    extern __shared__ char smem[];
    const uint32_t sb = (uint32_t)__cvta_generic_to_shared(smem);
    const int tid = threadIdx.x, wid = tid >> 5, lane = tid & 31;
    const int mt = blockIdx.x, c = blockIdx.y;
    const int row0 = mt * 128;
    const int wm = wid & 1, wn = wid >> 1;
    const int mbase = wm * 64, nbase = wn * 32;

    auto load_stage = [&](int st, int kt) {
        char* base = smem + st * G1S;
#pragma unroll
        for (int q = 0; q < 16; ++q) {
            const int i = tid + 128 * q, r = i >> 4, j = i & 15;
            cpasync16(base + r * 272 + j * 16,
                      U + (size_t)(row0 + r) * PTOT + c * 256 + kt * 64 + j * 4);
        }
#pragma unroll
        for (int q = 0; q < 4; ++q) {
            const int i = tid + 128 * q, r = i >> 3, k8 = i & 7;
            cpasync16(base + BH_OFF + swz(r, k8),
                      g_Sh + (size_t)c * 64 * 256 + (size_t)r * 256 + kt * 64 + k8 * 8);
        }
    };

    float acc[4][4][4];
#pragma unroll
    for (int mi = 0; mi < 4; ++mi)
#pragma unroll
        for (int ni = 0; ni < 4; ++ni)
#pragma unroll
            for (int q = 0; q < 4; ++q) acc[mi][ni][q] = 0.f;

    load_stage(0, 0); cpcommit();
    load_stage(1, 1); cpcommit();

    const int atile = lane >> 3;
    const int ar_off = (lane & 7) + (atile & 1) * 8;
    const int ak_off = atile >> 1;
    const int btt = lane & 15;
    const int br_off = btt & 7;
    const int bk_off = btt >> 3;

#pragma unroll 1
    for (int kt = 0; kt < 4; ++kt) {
        const int st = kt & 1;
        cpwait<1>(); __syncthreads();
        char* base = smem + st * G1S;
        const uint32_t tb = sb + st * G1S;

        {
            char* ah = base + AH_OFF;
            __half* gdst = g_Uh + (size_t)(row0 + tid) * PTOT + c * 256 + kt * 64;
#pragma unroll
            for (int k8 = 0; k8 < 8; ++k8) {
                const float4 a = *(const float4*)(base + tid * 272 + (2 * k8) * 16);
                const float4 b = *(const float4*)(base + tid * 272 + (2 * k8 + 1) * 16);
                uint4 v;
                v.x = h2u(__floats2half2_rn(a.x, a.y));
                v.y = h2u(__floats2half2_rn(a.z, a.w));
                v.z = h2u(__floats2half2_rn(b.x, b.y));
                v.w = h2u(__floats2half2_rn(b.z, b.w));
                *(uint4*)(ah + swz(tid, k8)) = v;
                *(uint4*)(gdst + k8 * 8) = v;
            }
        }
        __syncthreads();

#pragma unroll
        for (int ks = 0; ks < 4; ++ks) {
            uint32_t bh[4][2];
#pragma unroll
            for (int ni = 0; ni < 4; ++ni) {
                const int r = nbase + ni * 8 + br_off;
                ldmx2(bh[ni], tb + BH_OFF + swz(r, 2 * ks + bk_off));
            }
#pragma unroll
            for (int mi = 0; mi < 4; ++mi) {
                const int r = mbase + mi * 16 + ar_off;
                uint32_t ah[4];
                ldmx4(ah, tb + AH_OFF + swz(r, 2 * ks + ak_off));
#pragma unroll
                for (int ni = 0; ni < 4; ++ni)
                    mma16816(acc[mi][ni], ah, bh[ni]);
            }
        }
        __syncthreads();
        if (kt < 2) load_stage(st, kt + 2);
        cpcommit();
    }

#pragma unroll
    for (int mi = 0; mi < 4; ++mi) {
        const int r0 = row0 + mbase + mi * 16 + (lane >> 2);
#pragma unroll
        for (int ni = 0; ni < 4; ++ni) {
            const int n = nbase + ni * 8 + (lane & 3) * 2;
            float* d0 = g_xloc + ((size_t)r0 * NCH + c) * 64 + n;
            float* d1 = g_xloc + ((size_t)(r0 + 8) * NCH + c) * 64 + n;
            *(float2*)d0 = make_float2(acc[mi][ni][0], acc[mi][ni][1]);
            *(float2*)d1 = make_float2(acc[mi][ni][2], acc[mi][ni][3]);
        }
    }
}

// =====================================================================
// 4. Phase B v4: one WARP per (row, dir); lane owns one state entry.
//    x exchange via shfl (no block barriers on the chain);
//    P streamed per-chunk through an 8KB double buffer.
//    256 thr = 8 rows per CTA; grid (512, 2).
// =====================================================================
__global__ __launch_bounds__(256)
void phaseB_kernel() {
    __shared__ float sP[2][1024];
    const int tid = threadIdx.x, lane = tid & 31, wid = tid >> 5;
    const int d = blockIdx.y;
    const int row = blockIdx.x * 8 + wid;

    auto loadP = [&](int st, int ci) {
        const int c = d ? (NCH - 1 - ci) : ci;
        cpasync16(&((float4*)sP[st])[tid],
                  (const float4*)(g_P2 + (size_t)(d * NCH + c) * 1024) + tid);
    };
    loadP(0, 0); cpcommit();
    loadP(1, 1); cpcommit();

    float x = 0.f;
    float xlv = g_xloc[((size_t)row * NCH + (d ? NCH - 1 : 0)) * 64 + d * 32 + lane];

#pragma unroll 1
    for (int ci = 0; ci < NCH; ++ci) {
        const int c = d ? (NCH - 1 - ci) : ci;
        cpwait<1>(); __syncthreads();
        const float* P = sP[ci & 1];

        // xin = x at chunk entry
        g_xinh[((size_t)row * NCH + c) * 64 + d * 32 + lane] = __float2half_rn(x);

        // prefetch next xloc
        float xlnext = 0.f;
        if (ci + 1 < NCH) {
            const int cn = d ? (NCH - 1 - (ci + 1)) : (ci + 1);
            xlnext = g_xloc[((size_t)row * NCH + cn) * 64 + d * 32 + lane];
        }

        // x' = P x + xloc  (two interleaved partial sums to shorten FMA chain)
        float s0 = 0.f, s1 = 0.f;
#pragma unroll
        for (int j = 0; j < DS; j += 2) {
            const float xj0 = __shfl_sync(0xffffffffu, x, j);
            const float xj1 = __shfl_sync(0xffffffffu, x, j + 1);
            s0 = fmaf(P[j * 32 + lane], xj0, s0);
            s1 = fmaf(P[(j + 1) * 32 + lane], xj1, s1);
        }
        x = s0 + s1 + xlv;
        xlv = xlnext;

        __syncthreads();
        if (ci + 2 < NCH) loadP(ci & 1, ci + 2);
        cpcommit();
    }
}

// =====================================================================
// 5. GEMM2 (fp16 single-term): out[128x256] = A[128x320] x Th^T + bias
//    FULL N per CTA. 256 thr = 8 warps (2m x 4n), warp tile 64x64.
//    stage 48KB = A 16K | Bh 32K; 2 stages (96KB)
// =====================================================================
#define G2S 49152
__global__ __launch_bounds__(256)
void gemm2_kernel(const float* __restrict__ bias, float* __restrict__ out) {
    extern __shared__ char smem[];
    const uint32_t sb = (uint32_t)__cvta_generic_to_shared(smem);
    const int tid = threadIdx.x, wid = tid >> 5, lane = tid & 31;
    const int mt = blockIdx.x, c = blockIdx.y;
    const int row0 = mt * 128;
    const int wm = wid & 1, wn = wid >> 1;
    const int mbase = wm * 64, nbase = wn * 64;

    auto load_stage = [&](int st, int kt) {
        char* base = smem + st * G2S;
#pragma unroll
        for (int q = 0; q < 4; ++q) {
            const int i = tid + 256 * q, r = i >> 3, k8 = i & 7;
            const __half* src = (kt < 4)
                ? g_Uh + (size_t)(row0 + r) * PTOT + c * 256 + kt * 64 + k8 * 8
                : g_xinh + ((size_t)(row0 + r) * NCH + c) * 64 + k8 * 8;
            cpasync16(base + swz(r, k8), src);
        }
#pragma unroll
        for (int q = 0; q < 8; ++q) {
            const int i = tid + 256 * q, r = i >> 3, k8 = i & 7;
            const size_t g = (size_t)c * 256 * 320 + (size_t)r * 320 + kt * 64 + k8 * 8;
            cpasync16(base + 16384 + swz(r, k8), g_Th + g);
        }
    };

    float acc[4][8][4];
#pragma unroll
    for (int mi = 0; mi < 4; ++mi)
#pragma unroll
        for (int ni = 0; ni < 8; ++ni)
#pragma unroll
            for (int q = 0; q < 4; ++q) acc[mi][ni][q] = 0.f;

    load_stage(0, 0); cpcommit();
    load_stage(1, 1); cpcommit();

    const int atile = lane >> 3;
    const int ar_off = (lane & 7) + (atile & 1) * 8;
    const int ak_off = atile >> 1;
    const int btt = lane & 15;
    const int br_off = btt & 7;
    const int bk_off = btt >> 3;

#pragma unroll 1
    for (int kt = 0; kt < 5; ++kt) {
        const int st = kt & 1;
        cpwait<1>(); __syncthreads();
        const uint32_t tb = sb + st * G2S;
#pragma unroll
        for (int ks = 0; ks < 4; ++ks) {
            uint32_t bh[8][2];
#pragma unroll
            for (int ni = 0; ni < 8; ++ni) {
                const int r = nbase + ni * 8 + br_off;
                ldmx2(bh[ni], tb + 16384 + swz(r, 2 * ks + bk_off));
            }
#pragma unroll
            for (int mi = 0; mi < 4; ++mi) {
                const int r = mbase + mi * 16 + ar_off;
                uint32_t ah[4];
                ldmx4(ah, tb + swz(r, 2 * ks + ak_off));
#pragma unroll
                for (int ni = 0; ni < 8; ++ni)
                    mma16816(acc[mi][ni], ah, bh[ni]);
            }
        }
        __syncthreads();
        if (kt < 3) load_stage(st, kt + 2);
        cpcommit();
    }

#pragma unroll
    for (int mi = 0; mi < 4; ++mi) {
        const int r0 = row0 + mbase + mi * 16 + (lane >> 2);
#pragma unroll
        for (int ni = 0; ni < 8; ++ni) {
            const int n = nbase + ni * 8 + (lane & 3) * 2;
            const float2 bv = *(const float2*)(bias + c * 256 + n);
            float* d0 = out + (size_t)r0 * PTOT + c * 256 + n;
            float* d1 = out + (size_t)(r0 + 8) * PTOT + c * 256 + n;
            *(float2*)d0 = make_float2(acc[mi][ni][0] + bv.x, acc[mi][ni][1] + bv.y);
            *(float2*)d1 = make_float2(acc[mi][ni][2] + bv.x, acc[mi][ni][3] + bv.y);
        }
    }
}

// =====================================================================
extern "C" void kernel_launch(void* const* d_in, const int* in_sizes, int n_in,
                              void* d_out, int out_size) {
    const float* U    = (const float*)d_in[0];
    const float* A    = (const float*)d_in[1];
    const float* B    = (const float*)d_in[2];
    const float* C    = (const float*)d_in[3];
    const float* D    = (const float*)d_in[4];
    const float* E    = (const float*)d_in[5];
    const float* F    = (const float*)d_in[6];
    const float* G    = (const float*)d_in[7];
    const float* bias = (const float*)d_in[8];
    float* out = (float*)d_out;

    cudaFuncSetAttribute(gemm1_kernel, cudaFuncAttributeMaxDynamicSharedMemorySize, 2 * G1S);
    cudaFuncSetAttribute(gemm2_kernel, cudaFuncAttributeMaxDynamicSharedMemorySize, 2 * G2S);

    strip_kernel<<<dim3(NCH, LCH, 2), 128>>>(A, B, C, D, E, F, G);
    mn_kernel<<<dim3(NCH, 2), 256>>>(A, C, E, G);
    gemm1_kernel<<<dim3(BATCH / 128, NCH), 128, 2 * G1S>>>(U);
    phaseB_kernel<<<dim3(BATCH / 8, 2), 256>>>();
    gemm2_kernel<<<dim3(BATCH / 128, NCH), 256, 2 * G2S>>>(bias, out);
}